// round 12
// baseline (speedup 1.0000x reference)
#include <cuda_runtime.h>
#include <math.h>

#define HID   1024
#define SEQ   4096
#define G3    3072            // 3*HID
#define GIROWS 4098           // SEQ tokens + SOS row + EOS row
#define NBLK  128             // persistent CTAs (each handles BOTH dirs)
#define UPB   8               // hidden units per block (NBLK*UPB == HID)
#define RPB   24              // w_hh rows per block (3*UPB)
#define RPW   3               // rows per warp (8 warps * 3 == 24)

// ---------------- scratch (static device allocations only) ----------------
__device__ float g_GI[(size_t)GIROWS * G3];        // precomputed input gates (+b_ih)
// Self-synchronizing h: [dir][step parity][unit] = (tag<<32) | f32 bits,
// tag = step+1. One 8-byte word carries both the value and its readiness.
__device__ unsigned long long g_ht[2][2][HID];
__device__ int g_tok64;                            // 1 if tokens are int64

// ---------------- packed f32x2 helpers (sm_103a FFMA2 via PTX) ----------------
__device__ __forceinline__ unsigned long long ffma2(
    unsigned long long a, unsigned long long b, unsigned long long c)
{
    unsigned long long d;
    asm("fma.rn.f32x2 %0, %1, %2, %3;" : "=l"(d) : "l"(a), "l"(b), "l"(c));
    return d;
}
__device__ __forceinline__ float hsum_f32x2(unsigned long long p) {
    unsigned int lo, hi;
    asm("mov.b64 {%0, %1}, %2;" : "=r"(lo), "=r"(hi) : "l"(p));
    return __uint_as_float(lo) + __uint_as_float(hi);
}

// ---------------- gpu-scope relaxed 64-bit ld/st (L2-coherent) ----------------
__device__ __forceinline__ unsigned long long ld_relaxed_u64(const unsigned long long* p) {
    unsigned long long v;
    asm volatile("ld.relaxed.gpu.global.b64 %0, [%1];" : "=l"(v) : "l"(p) : "memory");
    return v;
}
__device__ __forceinline__ void st_relaxed_u64(unsigned long long* p, unsigned long long v) {
    asm volatile("st.relaxed.gpu.global.b64 [%0], %1;" :: "l"(p), "l"(v) : "memory");
}

// Zero all h tags (MUST run every launch: a previous replay leaves identical
// tag values that would falsely satisfy polls) + detect token dtype.
__global__ void setup_kernel(const int* toks_i32) {
    int i = blockIdx.x * blockDim.x + threadIdx.x;
    unsigned long long* ht = &g_ht[0][0][0];
    for (; i < 2 * 2 * HID; i += gridDim.x * blockDim.x) ht[i] = 0ull;
    if (blockIdx.x == 0 && threadIdx.x == 0) {
        int is64 = 1;
        for (int k = 0; k < 64; k++) {
            if (toks_i32[2 * k + 1] != 0 || toks_i32[2 * k] < 0) { is64 = 0; break; }
        }
        g_tok64 = is64;
    }
}

// ---------------- GI GEMM: GI[m][n] = b_ih[n] + emb[tok(m)] . w_ih[n] ----------------
__global__ __launch_bounds__(256) void gi_gemm_kernel(
    const void* __restrict__ toks_raw,
    const float* __restrict__ emb,
    const float* __restrict__ w_ih,
    const float* __restrict__ b_ih,
    int vocab)
{
    __shared__ float As[16][64];
    __shared__ float Bs[16][64];

    const int tx = threadIdx.x;       // 0..15
    const int ty = threadIdx.y;       // 0..15
    const int tid = ty * 16 + tx;
    const int m0 = blockIdx.y * 64;
    const int n0 = blockIdx.x * 64;

    const int lr = tid >> 2;          // 0..63 row within tile
    const int lk = (tid & 3) << 2;    // 0,4,8,12 k-offset

    const int am = m0 + lr;
    long long tok = 0;                // SOS row default
    if (am < SEQ) {
        if (g_tok64) tok = ((const long long*)toks_raw)[am];
        else         tok = (long long)((const int*)toks_raw)[am];
    }
    else if (am == SEQ)     tok = 0;  // SOS
    else if (am == SEQ + 1) tok = 1;  // EOS
    if (tok < 0) tok = 0;
    if (tok >= vocab) tok = vocab - 1;

    const float* Arow = emb + (size_t)tok * HID;
    const float* Brow = w_ih + (size_t)(n0 + lr) * HID;

    float c[4][4] = {};

    for (int k0 = 0; k0 < HID; k0 += 16) {
        float4 a = *(const float4*)(Arow + k0 + lk);
        float4 b = *(const float4*)(Brow + k0 + lk);
        As[lk + 0][lr] = a.x; As[lk + 1][lr] = a.y;
        As[lk + 2][lr] = a.z; As[lk + 3][lr] = a.w;
        Bs[lk + 0][lr] = b.x; Bs[lk + 1][lr] = b.y;
        Bs[lk + 2][lr] = b.z; Bs[lk + 3][lr] = b.w;
        __syncthreads();
        #pragma unroll
        for (int kk = 0; kk < 16; kk++) {
            float4 av = *(const float4*)&As[kk][ty << 2];
            float4 bv = *(const float4*)&Bs[kk][tx << 2];
            float ar[4] = {av.x, av.y, av.z, av.w};
            float br[4] = {bv.x, bv.y, bv.z, bv.w};
            #pragma unroll
            for (int i = 0; i < 4; i++)
                #pragma unroll
                for (int j = 0; j < 4; j++)
                    c[i][j] += ar[i] * br[j];
        }
        __syncthreads();
    }

    #pragma unroll
    for (int i = 0; i < 4; i++) {
        int m = m0 + (ty << 2) + i;
        if (m < GIROWS) {
            #pragma unroll
            for (int j = 0; j < 4; j++) {
                int n = n0 + (tx << 2) + j;
                g_GI[(size_t)m * G3 + n] = c[i][j] + b_ih[n];
            }
        }
    }
}

// ---------------- persistent recurrence, barrier-free tagged-h exchange --------
// 128 co-resident CTAs. Block handles 8 hidden units (24 w_hh rows) for BOTH
// directions. No grid barrier: each h element is published as an 8-byte
// (tag|value) word; consumers poll the words directly. Tag monotonicity plus
// parity double-buffering makes overrun impossible (a CTA can only advance to
// step t+2 after every CTA finished step t+1, hence finished reading buffer
// t&1). Zero fences: the 8-byte word is individually atomic.
__global__ __launch_bounds__(256, 1) void gru_rec_kernel(
    const float* __restrict__ w_hh,
    const float* __restrict__ b_hh,
    float* __restrict__ out)
{
    __shared__ __align__(16) float sh_h[2][HID];
    __shared__ float sh_gh[2][RPB];

    const int tid  = threadIdx.x;
    const int lane = tid & 31;
    const int warp = tid >> 5;
    const int j0   = blockIdx.x * UPB;

    // Register-cache this block's 24 w_hh rows as packed f32x2 pairs.
    ulonglong2 w[RPW][8];
    #pragma unroll
    for (int r = 0; r < RPW; r++) {
        int rr = warp * RPW + r;                      // 0..23
        int grow = (rr >> 3) * HID + j0 + (rr & 7);   // gate*HID + unit
        const ulonglong2* wp = (const ulonglong2*)(w_hh + (size_t)grow * HID);
        #pragma unroll
        for (int i = 0; i < 8; i++) w[r][i] = __ldg(wp + lane + 32 * i);
    }

    // Gating-thread constants (tid < 16): direction, unit, biases.
    const int d = tid >> 3;
    const int u = tid & 7;
    const int j = j0 + u;
    float bhr = 0.f, bhz = 0.f, bhn = 0.f;
    if (tid < 2 * UPB) {
        bhr = __ldg(b_hh + j);
        bhz = __ldg(b_hh + HID + j);
        bhn = __ldg(b_hh + 2 * HID + j);
    }

    float* outHid = out + HID;   // hiddens start after h_b

    for (int step = 0; step <= SEQ; step++) {
        // ---- GI prefetch (depends only on step; hides under the poll/dots) ----
        float ir = 0.f, iz = 0.f, inn = 0.f;
        if (tid < 2 * UPB) {
            int row = d ? (step == 0 ? SEQ + 1 : SEQ - step)
                        : (step == 0 ? SEQ     : step - 1);
            const float* gi = g_GI + (size_t)row * G3;
            ir  = __ldcg(gi + j);
            iz  = __ldcg(gi + HID + j);
            inn = __ldcg(gi + 2 * HID + j);
        }

        // ---- acquire previous h: poll tagged words directly ----
        if (step > 0) {
            const int p = (step - 1) & 1;
            const unsigned exptag = (unsigned)step;   // (step-1)+1
            const unsigned long long* s0 = &g_ht[0][p][4 * tid];
            const unsigned long long* s1 = &g_ht[1][p][4 * tid];
            float v[8];
            unsigned need = 0xFFu;
            do {
                #pragma unroll
                for (int k = 0; k < 8; k++) {
                    if (need & (1u << k)) {
                        const unsigned long long* s = (k < 4) ? (s0 + k) : (s1 + (k - 4));
                        unsigned long long x = ld_relaxed_u64(s);
                        if ((unsigned)(x >> 32) == exptag) {
                            v[k] = __uint_as_float((unsigned)x);
                            need &= ~(1u << k);
                        }
                    }
                }
            } while (need);
            #pragma unroll
            for (int k = 0; k < 4; k++) {
                sh_h[0][4 * tid + k] = v[k];
                sh_h[1][4 * tid + k] = v[4 + k];
            }
        } else {
            ((float4*)sh_h[0])[tid] = make_float4(0.f, 0.f, 0.f, 0.f);
            ((float4*)sh_h[1])[tid] = make_float4(0.f, 0.f, 0.f, 0.f);
        }
        __syncthreads();

        // ---- packed dot products: 24 rows x 2 dirs over 8 warps ----
        unsigned long long af[RPW][2] = {}, ab[RPW][2] = {};
        const ulonglong2* shf = (const ulonglong2*)sh_h[0];
        const ulonglong2* shb = (const ulonglong2*)sh_h[1];
        #pragma unroll
        for (int i = 0; i < 8; i++) {
            ulonglong2 hf = shf[lane + 32 * i];
            ulonglong2 hb = shb[lane + 32 * i];
            #pragma unroll
            for (int r = 0; r < RPW; r++) {
                af[r][0] = ffma2(w[r][i].x, hf.x, af[r][0]);
                af[r][1] = ffma2(w[r][i].y, hf.y, af[r][1]);
                ab[r][0] = ffma2(w[r][i].x, hb.x, ab[r][0]);
                ab[r][1] = ffma2(w[r][i].y, hb.y, ab[r][1]);
            }
        }
        float accf[RPW], accb[RPW];
        #pragma unroll
        for (int r = 0; r < RPW; r++) {
            accf[r] = hsum_f32x2(af[r][0]) + hsum_f32x2(af[r][1]);
            accb[r] = hsum_f32x2(ab[r][0]) + hsum_f32x2(ab[r][1]);
        }
        #pragma unroll
        for (int off = 16; off; off >>= 1) {
            #pragma unroll
            for (int r = 0; r < RPW; r++) {
                accf[r] += __shfl_xor_sync(0xffffffffu, accf[r], off);
                accb[r] += __shfl_xor_sync(0xffffffffu, accb[r], off);
            }
        }
        if (lane == 0) {
            #pragma unroll
            for (int r = 0; r < RPW; r++) {
                sh_gh[0][warp * RPW + r] = accf[r];
                sh_gh[1][warp * RPW + r] = accb[r];
            }
        }
        __syncthreads();

        // ---- gating: 16 threads, (dir, unit) = (tid>>3, tid&7) ----
        if (tid < 2 * UPB) {
            float ghr = sh_gh[d][u]           + bhr;
            float ghz = sh_gh[d][UPB + u]     + bhz;
            float ghn = sh_gh[d][2 * UPB + u] + bhn;
            float rg = __fdividef(1.f, 1.f + __expf(-(ir + ghr)));
            float zg = __fdividef(1.f, 1.f + __expf(-(iz + ghz)));
            float y  = inn + rg * ghn;
            y = fminf(fmaxf(y, -15.f), 15.f);
            float e2 = __expf(-2.f * y);
            float ng = __fdividef(1.f - e2, 1.f + e2);
            float hp = sh_h[d][j];
            float hn = (1.f - zg) * ng + zg * hp;
            // publish (tag | value) as one atomic 8-byte word
            unsigned long long pk =
                ((unsigned long long)(unsigned)(step + 1) << 32) |
                (unsigned long long)__float_as_uint(hn);
            st_relaxed_u64(&g_ht[d][step & 1][j], pk);
            if (step > 0) {
                int t = d ? (SEQ - step) : (step - 1);
                outHid[(size_t)t * (2 * HID) + d * HID + j] = hn;  // hiddens
                if (d == 1 && t == 0) out[j] = hn;                 // h_b
            }
        }

        // protect sh_h/sh_gh from next iteration's refill while gating reads them
        __syncthreads();
    }
}

// ---------------- launch ----------------
extern "C" void kernel_launch(void* const* d_in, const int* in_sizes, int n_in,
                              void* d_out, int out_size)
{
    const void*  toks = d_in[0];
    const float* emb  = (const float*)d_in[1];
    const float* w_ih = (const float*)d_in[2];
    const float* w_hh = (const float*)d_in[3];
    const float* b_ih = (const float*)d_in[4];
    const float* b_hh = (const float*)d_in[5];
    float*       out  = (float*)d_out;

    int vocab = in_sizes[1] / HID;   // emb rows

    setup_kernel<<<16, 256>>>((const int*)toks);
    gi_gemm_kernel<<<dim3(G3 / 64, (GIROWS + 63) / 64), dim3(16, 16)>>>(toks, emb, w_ih, b_ih, vocab);

    // Cooperative launch: guarantees all 128 CTAs co-resident (spin safety).
    cudaLaunchConfig_t cfg = {};
    cfg.gridDim = dim3(NBLK, 1, 1);
    cfg.blockDim = dim3(256, 1, 1);
    cfg.dynamicSmemBytes = 0;
    cfg.stream = 0;
    cudaLaunchAttribute attr[1];
    attr[0].id = cudaLaunchAttributeCooperative;
    attr[0].val.cooperative = 1;
    cfg.attrs = attr;
    cfg.numAttrs = 1;
    cudaLaunchKernelEx(&cfg, gru_rec_kernel, w_hh, b_hh, out);
}

// round 15
// speedup vs baseline: 1.1660x; 1.1660x over previous
#include <cuda_runtime.h>
#include <cooperative_groups.h>
#include <math.h>

namespace cg = cooperative_groups;

#define HID   1024
#define SEQ   4096
#define G3    3072            // 3*HID
#define GIROWS 4098           // SEQ tokens + SOS row + EOS row
#define NBLK  128             // persistent CTAs (each handles BOTH dirs)
#define UPB   8               // hidden units per block (NBLK*UPB == HID)
#define RPB   24              // w_hh rows per block (3*UPB)

// ---------------- scratch (static device allocations only) ----------------
__device__ float g_GI[(size_t)GIROWS * G3];   // precomputed input gates (+b_ih)
__device__ float g_h[2][2][HID];              // [dir][step parity][unit]
__device__ int   g_tok64;                     // 1 if tokens are int64

// ---------------- packed f32x2 helpers (sm_103a FFMA2 via PTX) ----------------
__device__ __forceinline__ unsigned long long ffma2(
    unsigned long long a, unsigned long long b, unsigned long long c)
{
    unsigned long long d;
    asm("fma.rn.f32x2 %0, %1, %2, %3;" : "=l"(d) : "l"(a), "l"(b), "l"(c));
    return d;
}
__device__ __forceinline__ float hsum_f32x2(unsigned long long p) {
    unsigned int lo, hi;
    asm("mov.b64 {%0, %1}, %2;" : "=r"(lo), "=r"(hi) : "l"(p));
    return __uint_as_float(lo) + __uint_as_float(hi);
}
__device__ __forceinline__ unsigned long long pack2(float x, float y) {
    unsigned long long p;
    asm("mov.b64 %0, {%1, %2};" : "=l"(p) : "r"(__float_as_uint(x)), "r"(__float_as_uint(y)));
    return p;
}

// Detect token dtype: int64 little-endian with values < 2^31 has all-zero
// high words; int32 data has random tokens there. P(misdetect) ~ (1/50257)^64.
__global__ void setup_kernel(const int* toks_i32) {
    if (blockIdx.x == 0 && threadIdx.x == 0) {
        int is64 = 1;
        for (int k = 0; k < 64; k++) {
            if (toks_i32[2 * k + 1] != 0 || toks_i32[2 * k] < 0) { is64 = 0; break; }
        }
        g_tok64 = is64;
    }
}

// ---------------- GI GEMM: GI[m][n] = b_ih[n] + emb[tok(m)] . w_ih[n] ----------------
// 64x64 tile, BK=16, 256 threads, 4x4 microtile per thread, FFMA2 inner loop.
__global__ __launch_bounds__(256) void gi_gemm_kernel(
    const void* __restrict__ toks_raw,
    const float* __restrict__ emb,
    const float* __restrict__ w_ih,
    const float* __restrict__ b_ih,
    int vocab)
{
    __shared__ float As[16][64];
    __shared__ float Bs[16][64];

    const int tx = threadIdx.x;       // 0..15
    const int ty = threadIdx.y;       // 0..15
    const int tid = ty * 16 + tx;
    const int m0 = blockIdx.y * 64;
    const int n0 = blockIdx.x * 64;

    const int lr = tid >> 2;          // 0..63 row within tile
    const int lk = (tid & 3) << 2;    // 0,4,8,12 k-offset

    const int am = m0 + lr;
    long long tok = 0;                // SOS row default
    if (am < SEQ) {
        if (g_tok64) tok = ((const long long*)toks_raw)[am];
        else         tok = (long long)((const int*)toks_raw)[am];
    }
    else if (am == SEQ)     tok = 0;  // SOS
    else if (am == SEQ + 1) tok = 1;  // EOS
    if (tok < 0) tok = 0;
    if (tok >= vocab) tok = vocab - 1;

    const float* Arow = emb + (size_t)tok * HID;
    const float* Brow = w_ih + (size_t)(n0 + lr) * HID;

    unsigned long long c2[4][2];
    #pragma unroll
    for (int i = 0; i < 4; i++) { c2[i][0] = 0ull; c2[i][1] = 0ull; }

    for (int k0 = 0; k0 < HID; k0 += 16) {
        float4 a = *(const float4*)(Arow + k0 + lk);
        float4 b = *(const float4*)(Brow + k0 + lk);
        As[lk + 0][lr] = a.x; As[lk + 1][lr] = a.y;
        As[lk + 2][lr] = a.z; As[lk + 3][lr] = a.w;
        Bs[lk + 0][lr] = b.x; Bs[lk + 1][lr] = b.y;
        Bs[lk + 2][lr] = b.z; Bs[lk + 3][lr] = b.w;
        __syncthreads();
        #pragma unroll
        for (int kk = 0; kk < 16; kk++) {
            float4 av = *(const float4*)&As[kk][ty << 2];
            float4 bv = *(const float4*)&Bs[kk][tx << 2];
            ulonglong2 b2 = *(ulonglong2*)&bv;   // (b0,b1),(b2,b3)
            float ar[4] = {av.x, av.y, av.z, av.w};
            #pragma unroll
            for (int i = 0; i < 4; i++) {
                unsigned long long aa = pack2(ar[i], ar[i]);
                c2[i][0] = ffma2(aa, b2.x, c2[i][0]);
                c2[i][1] = ffma2(aa, b2.y, c2[i][1]);
            }
        }
        __syncthreads();
    }

    #pragma unroll
    for (int i = 0; i < 4; i++) {
        int m = m0 + (ty << 2) + i;
        if (m < GIROWS) {
            float cv[4];
            unsigned int lo, hi;
            asm("mov.b64 {%0,%1}, %2;" : "=r"(lo), "=r"(hi) : "l"(c2[i][0]));
            cv[0] = __uint_as_float(lo); cv[1] = __uint_as_float(hi);
            asm("mov.b64 {%0,%1}, %2;" : "=r"(lo), "=r"(hi) : "l"(c2[i][1]));
            cv[2] = __uint_as_float(lo); cv[3] = __uint_as_float(hi);
            #pragma unroll
            for (int jj = 0; jj < 4; jj++) {
                int n = n0 + (tx << 2) + jj;
                g_GI[(size_t)m * G3 + n] = cv[jj] + b_ih[n];
            }
        }
    }
}

// ---------------- persistent recurrence, grid.sync() per step -----------------
// 128 cooperative CTAs; block handles 8 hidden units (24 w_hh rows) for BOTH
// directions. Warp grid: wkg = warp&3 owns K chunk [256*wkg, 256*wkg+256),
// wrg = warp>>2 owns rows [12*wrg, 12*wrg+12). Lane: ksub = lane&7 (K offset),
// rsub = lane>>3 (row within group of 4). Each lane's h slice (8 float4/dir)
// is register-resident, so the dot phase runs entirely out of registers.
// Per-(row,dir) partials: reduce over ksub (3 shfl levels), then a 4-way
// cross-warp (wkg) combine in SMEM folded into the gating phase.
// Output stores happen AFTER grid.sync (off the critical path).
__global__ __launch_bounds__(256, 1) void gru_rec_kernel(
    const float* __restrict__ w_hh,
    const float* __restrict__ b_hh,
    float* __restrict__ out)
{
    cg::grid_group grid = cg::this_grid();

    __shared__ __align__(16) float sh_h[2][HID];
    __shared__ float sh_part[2][4][RPB];   // [dir][wkg][row]

    const int tid  = threadIdx.x;
    const int lane = tid & 31;
    const int warp = tid >> 5;
    const int j0   = blockIdx.x * UPB;

    const int wkg  = warp & 3;        // K group: [256*wkg, 256*wkg+256)
    const int wrg  = warp >> 2;       // row group: [12*wrg, 12*wrg+12)
    const int ksub = lane & 7;        // K sub-offset within group
    const int rsub = lane >> 3;       // row within group-of-4

    // Register-cache weights: w4[p][i] = w_hh[row_p][256*wkg + 4*ksub + 32*i]
    // where row_p = 12*wrg + 4*p + rsub (p=0..2), global row via gate/unit map.
    float4 w4[3][8];
    #pragma unroll
    for (int p = 0; p < 3; p++) {
        int rr = 12 * wrg + 4 * p + rsub;              // 0..23
        int grow = (rr >> 3) * HID + j0 + (rr & 7);    // gate*HID + unit
        const float* wp = w_hh + (size_t)grow * HID + 256 * wkg + 4 * ksub;
        #pragma unroll
        for (int i = 0; i < 8; i++)
            w4[p][i] = *(const float4*)(wp + 32 * i);
    }

    // Gating-thread constants (tid < 16): direction, unit, biases.
    const int d = tid >> 3;
    const int u = tid & 7;
    const int j = j0 + u;
    float bhr = 0.f, bhz = 0.f, bhn = 0.f;
    if (tid < 2 * UPB) {
        bhr = __ldg(b_hh + j);
        bhz = __ldg(b_hh + HID + j);
        bhn = __ldg(b_hh + 2 * HID + j);
    }

    float* outHid = out + HID;   // hiddens start after h_b

    for (int step = 0; step <= SEQ; step++) {
        // ---- GI prefetch (depends only on step; hides under the dot phase) ----
        float ir = 0.f, iz = 0.f, inn = 0.f;
        if (tid < 2 * UPB) {
            int row = d ? (step == 0 ? SEQ + 1 : SEQ - step)
                        : (step == 0 ? SEQ     : step - 1);
            const float* gi = g_GI + (size_t)row * G3;
            ir  = __ldcg(gi + j);
            iz  = __ldcg(gi + HID + j);
            inn = __ldcg(gi + 2 * HID + j);
        }

        // ---- load previous h for both dirs (parity (step-1)&1), or zeros ----
        if (step > 0) {
            const int p = (step - 1) & 1;
            ((float4*)sh_h[0])[tid] = __ldcg((const float4*)g_h[0][p] + tid);
            ((float4*)sh_h[1])[tid] = __ldcg((const float4*)g_h[1][p] + tid);
        } else {
            ((float4*)sh_h[0])[tid] = make_float4(0.f, 0.f, 0.f, 0.f);
            ((float4*)sh_h[1])[tid] = make_float4(0.f, 0.f, 0.f, 0.f);
        }
        __syncthreads();

        // ---- stage this lane's h slice into registers (broadcast LDS) ----
        // float4 index: 64*wkg + ksub + 8*i  (8 distinct float4 per access)
        ulonglong2 hf[8], hb[8];
        {
            const ulonglong2* shf = (const ulonglong2*)sh_h[0];
            const ulonglong2* shb = (const ulonglong2*)sh_h[1];
            #pragma unroll
            for (int i = 0; i < 8; i++) {
                hf[i] = shf[64 * wkg + ksub + 8 * i];
                hb[i] = shb[64 * wkg + ksub + 8 * i];
            }
        }

        // ---- all-register packed dots: 3 row-passes x 8 K-iters ----
        float accf[3], accb[3];
        #pragma unroll
        for (int p = 0; p < 3; p++) {
            unsigned long long f2 = 0ull, b2 = 0ull;
            #pragma unroll
            for (int i = 0; i < 8; i++) {
                const ulonglong2 wv = *(const ulonglong2*)&w4[p][i];
                f2 = ffma2(wv.x, hf[i].x, f2);
                f2 = ffma2(wv.y, hf[i].y, f2);
                b2 = ffma2(wv.x, hb[i].x, b2);
                b2 = ffma2(wv.y, hb[i].y, b2);
            }
            accf[p] = hsum_f32x2(f2);
            accb[p] = hsum_f32x2(b2);
        }
        // reduce over ksub lanes (bits 0..2 of lane)
        #pragma unroll
        for (int off = 4; off; off >>= 1) {
            #pragma unroll
            for (int p = 0; p < 3; p++) {
                accf[p] += __shfl_xor_sync(0xffffffffu, accf[p], off);
                accb[p] += __shfl_xor_sync(0xffffffffu, accb[p], off);
            }
        }
        if (ksub == 0) {
            #pragma unroll
            for (int p = 0; p < 3; p++) {
                int rr = 12 * wrg + 4 * p + rsub;
                sh_part[0][wkg][rr] = accf[p];
                sh_part[1][wkg][rr] = accb[p];
            }
        }
        __syncthreads();

        // ---- gating: 16 threads, (dir, unit) = (tid>>3, tid&7) ----
        float hn = 0.f;
        if (tid < 2 * UPB) {
            float ghr = bhr, ghz = bhz, ghn = bhn;
            #pragma unroll
            for (int kg = 0; kg < 4; kg++) {
                ghr += sh_part[d][kg][u];            // gate r: row u
                ghz += sh_part[d][kg][8 + u];        // gate z: row 8+u
                ghn += sh_part[d][kg][16 + u];       // gate n: row 16+u
            }
            float rg = __fdividef(1.f, 1.f + __expf(-(ir + ghr)));
            float zg = __fdividef(1.f, 1.f + __expf(-(iz + ghz)));
            float y  = inn + rg * ghn;
            y = fminf(fmaxf(y, -15.f), 15.f);
            float e2 = __expf(-2.f * y);
            float ng = __fdividef(1.f - e2, 1.f + e2);
            float hp = sh_h[d][j];
            hn = (1.f - zg) * ng + zg * hp;
            __stcg(&g_h[d][step & 1][j], hn);   // publish BEFORE barrier
        }

        // ---- grid-wide release/acquire for this step ----
        grid.sync();

        // ---- output stores AFTER the barrier (off the critical path) ----
        if (tid < 2 * UPB && step > 0) {
            int t = d ? (SEQ - step) : (step - 1);
            outHid[(size_t)t * (2 * HID) + d * HID + j] = hn;  // hiddens
            if (d == 1 && t == 0) out[j] = hn;                 // h_b
        }
    }
}

// ---------------- launch ----------------
extern "C" void kernel_launch(void* const* d_in, const int* in_sizes, int n_in,
                              void* d_out, int out_size)
{
    const void*  toks = d_in[0];
    const float* emb  = (const float*)d_in[1];
    const float* w_ih = (const float*)d_in[2];
    const float* w_hh = (const float*)d_in[3];
    const float* b_ih = (const float*)d_in[4];
    const float* b_hh = (const float*)d_in[5];
    float*       out  = (float*)d_out;

    int vocab = in_sizes[1] / HID;   // emb rows

    setup_kernel<<<1, 32>>>((const int*)toks);
    gi_gemm_kernel<<<dim3(G3 / 64, (GIROWS + 63) / 64), dim3(16, 16)>>>(toks, emb, w_ih, b_ih, vocab);

    // Cooperative persistent recurrence (3 graph nodes total).
    cudaLaunchConfig_t cfg = {};
    cfg.gridDim = dim3(NBLK, 1, 1);
    cfg.blockDim = dim3(256, 1, 1);
    cfg.dynamicSmemBytes = 0;
    cfg.stream = 0;
    cudaLaunchAttribute attr[1];
    attr[0].id = cudaLaunchAttributeCooperative;
    attr[0].val.cooperative = 1;
    cfg.attrs = attr;
    cfg.numAttrs = 1;
    cudaLaunchKernelEx(&cfg, gru_rec_kernel, w_hh, b_hh, out);
}